// round 4
// baseline (speedup 1.0000x reference)
#include <cuda_runtime.h>
#include <math.h>

// Problem constants
#define TSTEPS 127   // 2W-1 skewed time steps
#define NB 8         // batch
#define NH 64        // H rows
#define NW 64        // W cols
#define HIDC 128     // hidden dim
#define OC 512       // 4*hid gate channels

// Scratch (device globals; no allocation allowed)
__device__ float g_zval[NB * NH * NW * OC];                 // [b][p][col][oc]
__device__ float g_hhist[(size_t)TSTEPS * NB * NH * HIDC]; // [t][b][p][c]
__device__ unsigned g_cnt[TSTEPS * 32];                    // [t][rowgroup] arrival counters

// ---------------- PTX helpers ----------------
__device__ __forceinline__ unsigned smem_u32(const void* p) {
    unsigned a;
    asm("{ .reg .u64 t; cvta.to.shared.u64 t, %1; cvt.u32.u64 %0, t; }"
        : "=r"(a) : "l"(p));
    return a;
}
__device__ __forceinline__ unsigned long long lds_b64(unsigned a) {
    unsigned long long v;
    asm volatile("ld.shared.b64 %0, [%1];" : "=l"(v) : "r"(a));
    return v;
}
__device__ __forceinline__ void lds_v2b64(unsigned a, unsigned long long& x, unsigned long long& y) {
    asm volatile("ld.shared.v2.b64 {%0,%1}, [%2];" : "=l"(x), "=l"(y) : "r"(a));
}
__device__ __forceinline__ void sts_dupf(unsigned a, float v) {
    asm volatile("st.shared.v2.f32 [%0], {%1,%1};" :: "r"(a), "f"(v) : "memory");
}
__device__ __forceinline__ void ffma2(unsigned long long& d, unsigned long long a, unsigned long long b) {
    asm volatile("fma.rn.f32x2 %0, %1, %2, %0;" : "+l"(d) : "l"(a), "l"(b));
}
__device__ __forceinline__ float2 unpk2(unsigned long long v) {
    float2 r;
    asm("mov.b64 {%0,%1}, %2;" : "=f"(r.x), "=f"(r.y) : "l"(v));
    return r;
}
__device__ __forceinline__ unsigned ld_acquire_gpu(const unsigned* p) {
    unsigned v;
    asm volatile("ld.acquire.gpu.u32 %0, [%1];" : "=r"(v) : "l"(p) : "memory");
    return v;
}
__device__ __forceinline__ float fsig(float x) {
    return __fdividef(1.0f, 1.0f + __expf(-x));
}
__device__ __forceinline__ float ftanh_(float x) {
    float e = __expf(2.0f * x);
    return 1.0f - __fdividef(2.0f, e + 1.0f);
}

// ---------------------------------------------------------------------------
// Kernel 1: input-to-state 1x1 conv as GEMM (FFMA2 version).
//   Z[m][o] = sum_c x[b][c][p][col] * w_is[o][c] + b_is[o]
// M = 32768, K = 128, N = 512.  Grid: 1024 = 256 m-tiles x 4 n-tiles.
// smem: Xs duplicated pairs {x,x} [128k][128m][2] = 128KB; Ws [128k][128o] = 64KB.
// ---------------------------------------------------------------------------
__global__ void __launch_bounds__(256) k_zval(const float* __restrict__ x,
                                              const float* __restrict__ w_is,
                                              const float* __restrict__ b_is) {
    extern __shared__ float sm1[];
    float* Xs2 = sm1;          // 32768 floats (dup pairs)
    float* Ws  = sm1 + 32768;  // 16384 floats
    const int tid = threadIdx.x;

    if (blockIdx.x == 0) {
        for (int i = tid; i < TSTEPS * 32; i += 256) g_cnt[i] = 0u;
    }

    const int mt = blockIdx.x >> 2;
    const int nt = blockIdx.x & 3;
    const int m0 = mt * 128;
    const int n0 = nt * 128;
    const int b  = m0 >> 12;
    const int rem = m0 & 4095;
    const float* xb = x + (size_t)b * 128 * 4096 + rem;

    const unsigned xs_base = smem_u32(Xs2);
    const unsigned ws_base = smem_u32(Ws);

    // load X tile duplicated: Xs2[(c*128+mi)*2 + {0,1}] = x
    for (int i = tid * 4; i < 16384; i += 1024) {
        int c = i >> 7, mi = i & 127;
        float4 v = *reinterpret_cast<const float4*>(xb + (size_t)c * 4096 + mi);
        unsigned a = xs_base + (unsigned)((c * 128 + mi) * 8);
        sts_dupf(a, v.x);
        sts_dupf(a + 8, v.y);
        sts_dupf(a + 16, v.z);
        sts_dupf(a + 24, v.w);
    }
    // load W tile transposed: Ws[c][oi]
    for (int i = tid * 4; i < 16384; i += 1024) {
        int oi = i >> 7, c4 = i & 127;
        float4 v = *reinterpret_cast<const float4*>(w_is + (size_t)(n0 + oi) * 128 + c4);
        Ws[(c4 + 0) * 128 + oi] = v.x;
        Ws[(c4 + 1) * 128 + oi] = v.y;
        Ws[(c4 + 2) * 128 + oi] = v.z;
        Ws[(c4 + 3) * 128 + oi] = v.w;
    }
    __syncthreads();

    const int tx = tid & 15, ty = tid >> 4;
    const int mi0 = ty * 8, oi0 = tx * 8;

    unsigned long long acc[8][4];
#pragma unroll
    for (int r = 0; r < 8; ++r)
#pragma unroll
        for (int j = 0; j < 4; ++j) acc[r][j] = 0ULL;

    const unsigned xa0 = xs_base + (unsigned)(mi0 * 8);
    const unsigned wa0 = ws_base + (unsigned)(oi0 * 4);

#pragma unroll 4
    for (int k = 0; k < 128; ++k) {
        unsigned xa = xa0 + (unsigned)(k * 1024);
        unsigned wa = wa0 + (unsigned)(k * 512);
        unsigned long long a01, a23, a45, a67, a89, aab, acd, aef;
        lds_v2b64(xa,      a01, a23);
        lds_v2b64(xa + 16, a45, a67);
        lds_v2b64(xa + 32, a89, aab);
        lds_v2b64(xa + 48, acd, aef);
        unsigned long long w0, w1, w2, w3;
        lds_v2b64(wa,      w0, w1);
        lds_v2b64(wa + 16, w2, w3);
        unsigned long long ar[8] = {a01, a23, a45, a67, a89, aab, acd, aef};
#pragma unroll
        for (int r = 0; r < 8; ++r) {
            ffma2(acc[r][0], ar[r], w0);
            ffma2(acc[r][1], ar[r], w1);
            ffma2(acc[r][2], ar[r], w2);
            ffma2(acc[r][3], ar[r], w3);
        }
    }

    float bias[8];
#pragma unroll
    for (int c = 0; c < 8; ++c) bias[c] = b_is[n0 + oi0 + c];

#pragma unroll
    for (int r = 0; r < 8; ++r) {
        float* op = g_zval + (size_t)(m0 + mi0 + r) * OC + n0 + oi0;
        float2 p0 = unpk2(acc[r][0]), p1 = unpk2(acc[r][1]);
        float2 p2 = unpk2(acc[r][2]), p3 = unpk2(acc[r][3]);
        float4 v0, v1;
        v0.x = p0.x + bias[0]; v0.y = p0.y + bias[1];
        v0.z = p1.x + bias[2]; v0.w = p1.y + bias[3];
        v1.x = p2.x + bias[4]; v1.y = p2.y + bias[5];
        v1.z = p3.x + bias[6]; v1.w = p3.y + bias[7];
        *reinterpret_cast<float4*>(op)     = v0;
        *reinterpret_cast<float4*>(op + 4) = v1;
    }
}

// ---------------------------------------------------------------------------
// Kernel 2: persistent recurrence (FFMA2 + broadcast-friendly lane mapping).
// Grid = 128 blocks: blockIdx.x = rg*4 + cg
//   cg in [0,4): channel group (128 of 512 gate channels)
//   rg in [0,32): rg = b*4 + pblk, rows p in [16*pblk, 16*pblk+16)
// GEMM lane map: warp w, lane l: r = l&15, colhalf = l>>4, c0 = w*16 + colhalf*8.
// Each lane: 1 row x 8 cols, cols as 4 f32x2 accumulators.
// smem: Wsm [256k][128ol] 128KB; hs2 dup pairs [256k][16r][2] stride 34;
//       zsm [16r][132].
// ---------------------------------------------------------------------------
__global__ void __launch_bounds__(256) k_recur(const float* __restrict__ w_ss,
                                               const float* __restrict__ b_is,
                                               const float* __restrict__ b_ss) {
    extern __shared__ float sm[];
    float* Wsm = sm;                  // 32768 floats
    float* hs2 = sm + 32768;          // 256*34 = 8704 floats (dup pairs, stride 34)
    float* zsm = sm + 32768 + 8704;   // 16*132 = 2112 floats

    const int tid  = threadIdx.x;
    const int cg   = blockIdx.x & 3;
    const int rg   = blockIdx.x >> 2;
    const int bb   = rg >> 2;
    const int pblk = rg & 3;
    const int p0   = pblk * 16;

    const unsigned wbase = smem_u32(Wsm);
    const unsigned hbase = smem_u32(hs2);

    // --- prologue: weight slice into smem ---
    for (int idx = tid; idx < 128 * 128; idx += 256) {
        int i  = idx & 127;
        int ol = idx >> 7;
        int og = ((ol >> 5) * 128) + cg * 32 + (ol & 31);
        float2 v = *reinterpret_cast<const float2*>(w_ss + (size_t)og * 256 + i * 2);
        Wsm[i * 128 + ol]         = v.x;  // kh=0 (prev row) -> k = i
        Wsm[(i + 128) * 128 + ol] = v.y;  // kh=1 (cur row)  -> k = i+128
    }

    // GEMM lane mapping
    const int w  = tid >> 5;
    const int l  = tid & 31;
    const int r  = l & 15;
    const int c0 = w * 16 + (l >> 4) * 8;               // local out col base (mult of 8)
    const int og0 = ((c0 >> 5) * 128) + cg * 32 + (c0 & 31);
    const int myp = p0 + r;

    float4 bregA  = *reinterpret_cast<const float4*>(b_ss + og0);
    float4 bregB  = *reinterpret_cast<const float4*>(b_ss + og0 + 4);
    float4 biregA = *reinterpret_cast<const float4*>(b_is + og0);
    float4 biregB = *reinterpret_cast<const float4*>(b_is + og0 + 4);

    // gate-phase state mapping: states s = 2*tid, 2*tid+1 -> (row, channel)
    const int srow = tid >> 4;          // 0..15
    const int sj0  = (2 * tid) & 31;    // even channel within 32-group
    float cst0 = 0.0f, cst1 = 0.0f;

    const unsigned ha0 = hbase + (unsigned)(r * 8);
    const unsigned wa0 = wbase + (unsigned)(c0 * 4);

    __syncthreads();

    for (int t = 0; t < TSTEPS; ++t) {
        // --- prefetch z baseline (1 row x 8 channels) ---
        float4 zA, zB;
        {
            int col = t - myp;
            if (col >= 0 && col < NW) {
                const float* zp = g_zval + (((size_t)(bb * NH + myp) * NW + col) * OC) + og0;
                zA = *reinterpret_cast<const float4*>(zp);
                zB = *reinterpret_cast<const float4*>(zp + 4);
            } else {
                zA = biregA; zB = biregB;
            }
        }

        unsigned long long acc0 = 0ULL, acc1 = 0ULL, acc2 = 0ULL, acc3 = 0ULL;

        if (t > 0) {
            // --- wait for h[t-1] producers ---
            if (tid == 0) {
                const unsigned* c1 = &g_cnt[(t - 1) * 32 + rg];
                while (ld_acquire_gpu(c1) < 4u) {}
                if (pblk > 0) {
                    const unsigned* c2 = c1 - 1;
                    while (ld_acquire_gpu(c2) < 4u) {}
                }
            }
            __syncthreads();

            // --- stage h rows into duplicated smem pairs ---
            const float* hb = g_hhist + ((size_t)(t - 1) * NB + bb) * NH * HIDC;
            for (int idx = tid; idx < 2048; idx += 256) {
                int rr = idx >> 7;       // 0..15
                int c  = idx & 127;
                float vc = hb[(size_t)(p0 + rr) * HIDC + c];
                int rp = p0 + rr - 1;
                float vp = (rp >= 0) ? hb[(size_t)rp * HIDC + c] : 0.0f;
                sts_dupf(hbase + (unsigned)(((c + 128) * 34 + rr * 2) * 4), vc);
                sts_dupf(hbase + (unsigned)((c * 34 + rr * 2) * 4), vp);
            }
            __syncthreads();

            // --- GEMM: 256 k-taps, 4 f32x2 accumulators ---
#pragma unroll 8
            for (int k = 0; k < 256; ++k) {
                unsigned long long h2 = lds_b64(ha0 + (unsigned)(k * 136));
                unsigned long long w0, w1, w2, w3;
                unsigned wa = wa0 + (unsigned)(k * 512);
                lds_v2b64(wa,      w0, w1);
                lds_v2b64(wa + 16, w2, w3);
                ffma2(acc0, h2, w0);
                ffma2(acc1, h2, w1);
                ffma2(acc2, h2, w2);
                ffma2(acc3, h2, w3);
            }
        }

        // --- combine + stage pre-activations ---
        {
            float2 p0f = unpk2(acc0), p1f = unpk2(acc1);
            float2 p2f = unpk2(acc2), p3f = unpk2(acc3);
            float4 z0, z1;
            z0.x = p0f.x + zA.x + bregA.x;
            z0.y = p0f.y + zA.y + bregA.y;
            z0.z = p1f.x + zA.z + bregA.z;
            z0.w = p1f.y + zA.w + bregA.w;
            z1.x = p2f.x + zB.x + bregB.x;
            z1.y = p2f.y + zB.y + bregB.y;
            z1.z = p3f.x + zB.z + bregB.z;
            z1.w = p3f.y + zB.w + bregB.w;
            float* zp = &zsm[r * 132 + c0];
            *reinterpret_cast<float4*>(zp)     = z0;
            *reinterpret_cast<float4*>(zp + 4) = z1;
        }
        __syncthreads();

        // --- gates + state update (2 states per thread) ---
        {
            const float* zr = &zsm[srow * 132];
            float h0, h1;
            {
                float zi = zr[sj0],      zf = zr[32 + sj0];
                float zo = zr[64 + sj0], zg = zr[96 + sj0];
                float ig = fsig(zi), fg = fsig(zf);
                float ogt = fsig(zo), gg = ftanh_(zg);
                cst0 = fg * cst0 + ig * gg;
                h0 = ogt * ftanh_(cst0);
            }
            {
                int j = sj0 + 1;
                float zi = zr[j],      zf = zr[32 + j];
                float zo = zr[64 + j], zg = zr[96 + j];
                float ig = fsig(zi), fg = fsig(zf);
                float ogt = fsig(zo), gg = ftanh_(zg);
                cst1 = fg * cst1 + ig * gg;
                h1 = ogt * ftanh_(cst1);
            }
            int p = p0 + srow;
            float* hw = g_hhist + (((size_t)t * NB + bb) * NH + p) * HIDC + cg * 32 + sj0;
            float2 hv; hv.x = h0; hv.y = h1;
            *reinterpret_cast<float2*>(hw) = hv;
        }

        __syncthreads();
        if (tid == 0) {
            __threadfence();   // cumulative: orders all block's h stores (via bar) at gpu scope
            atomicAdd(&g_cnt[t * 32 + rg], 1u);
        }
    }
}

// ---------------------------------------------------------------------------
// Kernel 3: unskew + transpose into output layout (B, hid, H, W).
//   out[b][c][p][col] = g_hhist[t = p+col][b][p][c]
// ---------------------------------------------------------------------------
__global__ void __launch_bounds__(256) k_unskew(float* __restrict__ out) {
    __shared__ float tile[64 * 129];
    const int bp = blockIdx.x;
    const int b = bp >> 6, p = bp & 63;
    const int tid = threadIdx.x;

    for (int idx = tid; idx < 64 * 128; idx += 256) {
        int col = idx >> 7, c = idx & 127;
        int t = p + col;
        tile[col * 129 + c] = g_hhist[(((size_t)t * NB + b) * NH + p) * HIDC + c];
    }
    __syncthreads();
    for (int idx = tid; idx < 64 * 128; idx += 256) {
        int c = idx >> 6, col = idx & 63;
        out[(((size_t)b * HIDC + c) * NH + p) * NW + col] = tile[col * 129 + c];
    }
}

// ---------------------------------------------------------------------------
extern "C" void kernel_launch(void* const* d_in, const int* in_sizes, int n_in,
                              void* d_out, int out_size) {
    const float* x    = (const float*)d_in[0];  // (8,128,64,64)
    const float* w_is = (const float*)d_in[1];  // (512,128)
    const float* b_is = (const float*)d_in[2];  // (512,)
    const float* w_ss = (const float*)d_in[3];  // (512,128,2,1)
    const float* b_ss = (const float*)d_in[4];  // (512,)
    float* out = (float*)d_out;                 // (8,128,64,64)

    cudaFuncSetAttribute(k_zval, cudaFuncAttributeMaxDynamicSharedMemorySize, 196608);
    cudaFuncSetAttribute(k_recur, cudaFuncAttributeMaxDynamicSharedMemorySize, 174336);

    k_zval<<<1024, 256, 196608>>>(x, w_is, b_is);
    k_recur<<<128, 256, 174336>>>(w_ss, b_is, b_ss);
    k_unskew<<<512, 256>>>(out);

    (void)in_sizes; (void)n_in; (void)out_size;
}